// round 4
// baseline (speedup 1.0000x reference)
#include <cuda_runtime.h>
#include <mma.h>

using namespace nvcuda;

#define D_MODEL   2048
#define FFN_DIM   8192
#define HALF_FFN  4096
#define NE        8
#define T_TOKENS  8192
#define MAXROWS   (T_TOKENS * 2)

#define BM 128
#define BN 128
#define BK 32
#define LDS 36                 // 32 + 4 pad (keeps 32B-aligned fragment rows)
#define GEMM_THREADS 256
#define GEMM_SMEM 65536        // max(A+B stage = 36864B, C stage = 65536B)

// ---------------- scratch (device globals; no runtime allocation) ----------
__device__ float g_H[(size_t)MAXROWS * FFN_DIM];          // 512 MB: up-proj outputs
__device__ float g_Y[(size_t)2 * T_TOKENS * D_MODEL];     // 128 MB: per-slot down outputs
__device__ int   g_topk_idx[T_TOKENS][2];
__device__ float g_topk_w[T_TOKENS][2];
__device__ int   g_count[NE];
__device__ int   g_offs[NE + 1];
__device__ int   g_tile_offs[NE + 1];
__device__ int   g_list_token[MAXROWS];
__device__ int   g_list_slot[MAXROWS];
__device__ float g_list_coef[MAXROWS];

// ---------------- routing ---------------------------------------------------
__global__ void reset_kernel() {
    if (threadIdx.x < NE) g_count[threadIdx.x] = 0;
}

__global__ void routing_kernel(const float* __restrict__ x,
                               const float* __restrict__ gate_w) {
    int gwarp = (blockIdx.x * blockDim.x + threadIdx.x) >> 5;
    int lane  = threadIdx.x & 31;
    if (gwarp >= T_TOKENS) return;

    const float* xr = x + (size_t)gwarp * D_MODEL;
    float acc[NE];
#pragma unroll
    for (int e = 0; e < NE; e++) acc[e] = 0.f;

    for (int k = lane; k < D_MODEL; k += 32) {
        float xv = xr[k];
#pragma unroll
        for (int e = 0; e < NE; e++) acc[e] += xv * gate_w[e * D_MODEL + k];
    }
#pragma unroll
    for (int off = 16; off > 0; off >>= 1) {
#pragma unroll
        for (int e = 0; e < NE; e++)
            acc[e] += __shfl_xor_sync(0xffffffffu, acc[e], off);
    }
    if (lane == 0) {
        int i0 = 0; float b0 = acc[0];
#pragma unroll
        for (int i = 1; i < NE; i++) if (acc[i] > b0) { b0 = acc[i]; i0 = i; }
        int i1 = -1; float b1 = -3.0e38f;
#pragma unroll
        for (int i = 0; i < NE; i++)
            if (i != i0 && acc[i] > b1) { b1 = acc[i]; i1 = i; }

        // weights = renormalized top-2 softmax = 2-way softmax of the top-2 logits
        float e1  = expf(b1 - b0);
        float inv = 1.f / (1.f + e1);
        g_topk_idx[gwarp][0] = i0;  g_topk_idx[gwarp][1] = i1;
        g_topk_w[gwarp][0]   = inv; g_topk_w[gwarp][1]   = e1 * inv;
        atomicAdd(&g_count[i0], 1);
        atomicAdd(&g_count[i1], 1);
    }
}

__global__ void offs_kernel() {
    if (threadIdx.x == 0 && blockIdx.x == 0) {
        int off = 0, toff = 0;
        for (int e = 0; e < NE; e++) {
            g_offs[e] = off; g_tile_offs[e] = toff;
            off  += g_count[e];
            toff += (g_count[e] + BM - 1) >> 7;
        }
        g_offs[NE] = off; g_tile_offs[NE] = toff;
    }
}

// deterministic stream compaction: one block per expert, block-wide scan
__global__ void compact_kernel() {
    int e   = blockIdx.x;
    int tid = threadIdx.x;
    __shared__ int s[1024];

    int base = g_offs[e];
    int run  = 0;
    for (int c0 = 0; c0 < T_TOKENS; c0 += 1024) {
        int t = c0 + tid;
        int sel = 0, slot = 0; float w = 0.f;
        if (t < T_TOKENS) {
            int i0 = g_topk_idx[t][0], i1 = g_topk_idx[t][1];
            if (i0 == e)      { sel = 1; slot = 0; w = g_topk_w[t][0]; }
            else if (i1 == e) { sel = 1; slot = 1; w = g_topk_w[t][1]; }
        }
        s[tid] = sel; __syncthreads();
        for (int d = 1; d < 1024; d <<= 1) {
            int v = (tid >= d) ? s[tid - d] : 0;
            __syncthreads();
            s[tid] += v;
            __syncthreads();
        }
        int incl  = s[tid];
        int total = s[1023];
        if (sel) {
            int r = base + run + incl - 1;
            g_list_token[r] = t;
            g_list_slot[r]  = slot;
            g_list_coef[r]  = w;
        }
        run += total;
        __syncthreads();
    }
}

// ---------------- TF32 wmma GEMM machinery ----------------------------------
using FragA = wmma::fragment<wmma::matrix_a, 16, 16, 8, wmma::precision::tf32, wmma::row_major>;
using FragB = wmma::fragment<wmma::matrix_b, 16, 16, 8, wmma::precision::tf32, wmma::col_major>;
using FragC = wmma::fragment<wmma::accumulator, 16, 16, 8, float>;

template <typename Frag>
__device__ __forceinline__ void to_tf32(Frag& f) {
#pragma unroll
    for (int i = 0; i < f.num_elements; i++) f.x[i] = wmma::__float_to_tf32(f.x[i]);
}

__device__ __forceinline__ int find_expert(int ytile) {
    int e = 0;
#pragma unroll
    for (int i = 0; i < NE; i++) if (ytile >= g_tile_offs[i + 1]) e = i + 1;
    return e;
}

// C[m][n] = sum_k gather(X)[m][k] * Wup[n][k]   -> g_H rows
__global__ void __launch_bounds__(GEMM_THREADS, 1)
up_gemm_kernel(const float* __restrict__ x, const float* __restrict__ w_up) {
    int ytile = blockIdx.y;
    if (ytile >= g_tile_offs[NE]) return;
    int e  = find_expert(ytile);
    int m0 = (ytile - g_tile_offs[e]) * BM;
    int cnt = g_count[e];
    int rows_valid = cnt - m0; if (rows_valid > BM) rows_valid = BM;
    int base = g_offs[e];
    int n0   = blockIdx.x * BN;
    int tid  = threadIdx.x;

    __shared__ int s_token[BM];
    if (tid < BM) {
        int r = tid;
        s_token[r] = g_list_token[base + m0 + ((r < rows_valid) ? r : 0)];
    }
    __syncthreads();

    extern __shared__ float smem[];
    float* As = smem;                 // [BM][LDS]
    float* Bs = smem + BM * LDS;      // [BN][LDS]
    float* Cs = smem;                 // reused: [BM][BN]

    const float* wexp = w_up + (size_t)e * FFN_DIM * D_MODEL;

    int lr = tid >> 3;            // 0..31
    int lc = (tid & 7) * 4;       // 0..28
    const float* aptr[4];
    const float* bptr[4];
#pragma unroll
    for (int p = 0; p < 4; p++) {
        int row = lr + 32 * p;
        aptr[p] = x    + (size_t)s_token[row] * D_MODEL + lc;
        bptr[p] = wexp + (size_t)(n0 + row)   * D_MODEL + lc;
    }

    int warpId = tid >> 5;
    int wm = (warpId & 3) * 32;
    int wn = (warpId >> 2) * 64;

    FragC acc[2][4];
#pragma unroll
    for (int i = 0; i < 2; i++)
#pragma unroll
        for (int j = 0; j < 4; j++) wmma::fill_fragment(acc[i][j], 0.f);

    float4 ra[4], rb[4];
#pragma unroll
    for (int p = 0; p < 4; p++) {
        ra[p] = *(const float4*)(aptr[p]);
        rb[p] = *(const float4*)(bptr[p]);
    }

    const int KT = D_MODEL / BK;   // 64
#pragma unroll 1
    for (int kt = 0; kt < KT; kt++) {
#pragma unroll
        for (int p = 0; p < 4; p++) {
            int row = lr + 32 * p;
            *(float4*)(As + row * LDS + lc) = ra[p];
            *(float4*)(Bs + row * LDS + lc) = rb[p];
        }
        __syncthreads();
        if (kt + 1 < KT) {
            int k0 = (kt + 1) * BK;
#pragma unroll
            for (int p = 0; p < 4; p++) {
                ra[p] = *(const float4*)(aptr[p] + k0);
                rb[p] = *(const float4*)(bptr[p] + k0);
            }
        }
#pragma unroll
        for (int ks = 0; ks < BK / 8; ks++) {
            FragA af[2]; FragB bf[4];
#pragma unroll
            for (int i = 0; i < 2; i++) {
                wmma::load_matrix_sync(af[i], As + (wm + i * 16) * LDS + ks * 8, LDS);
                to_tf32(af[i]);
            }
#pragma unroll
            for (int j = 0; j < 4; j++) {
                wmma::load_matrix_sync(bf[j], Bs + (wn + j * 16) * LDS + ks * 8, LDS);
                to_tf32(bf[j]);
            }
#pragma unroll
            for (int i = 0; i < 2; i++)
#pragma unroll
                for (int j = 0; j < 4; j++)
                    wmma::mma_sync(acc[i][j], af[i], bf[j], acc[i][j]);
        }
        __syncthreads();
    }

#pragma unroll
    for (int i = 0; i < 2; i++)
#pragma unroll
        for (int j = 0; j < 4; j++)
            wmma::store_matrix_sync(Cs + (wm + i * 16) * BN + (wn + j * 16),
                                    acc[i][j], BN, wmma::mem_row_major);
    __syncthreads();

#pragma unroll
    for (int p = 0; p < 16; p++) {
        int idx = tid + p * 256;
        int row = idx >> 5;
        int col = (idx & 31) * 4;
        if (row < rows_valid) {
            *(float4*)(g_H + (size_t)(base + m0 + row) * FFN_DIM + n0 + col) =
                *(const float4*)(Cs + row * BN + col);
        }
    }
}

// C[m][n] = sum_k silu(H[m][k])*H[m][k+HALF] * Wdown[n][k], scaled by coef -> g_Y[slot]
__global__ void __launch_bounds__(GEMM_THREADS, 1)
down_gemm_kernel(const float* __restrict__ w_down) {
    int ytile = blockIdx.y;
    if (ytile >= g_tile_offs[NE]) return;
    int e  = find_expert(ytile);
    int m0 = (ytile - g_tile_offs[e]) * BM;
    int cnt = g_count[e];
    int rows_valid = cnt - m0; if (rows_valid > BM) rows_valid = BM;
    int base = g_offs[e];
    int n0   = blockIdx.x * BN;
    int tid  = threadIdx.x;

    __shared__ int   s_tok[BM];
    __shared__ int   s_slot[BM];
    __shared__ float s_coef[BM];
    if (tid < BM) {
        int r = tid;
        if (r < rows_valid) {
            s_tok[r]  = g_list_token[base + m0 + r];
            s_slot[r] = g_list_slot[base + m0 + r];
            s_coef[r] = g_list_coef[base + m0 + r];
        } else {
            s_tok[r] = 0; s_slot[r] = 0; s_coef[r] = 0.f;
        }
    }
    __syncthreads();

    extern __shared__ float smem[];
    float* As = smem;
    float* Bs = smem + BM * LDS;
    float* Cs = smem;

    const float* wexp = w_down + (size_t)e * D_MODEL * HALF_FFN;

    int lr = tid >> 3;
    int lc = (tid & 7) * 4;
    const float* hptr[4];
    const float* bptr[4];
#pragma unroll
    for (int p = 0; p < 4; p++) {
        int row = lr + 32 * p;
        int rr  = (row < rows_valid) ? row : (rows_valid - 1);
        hptr[p] = g_H  + (size_t)(base + m0 + rr) * FFN_DIM  + lc;
        bptr[p] = wexp + (size_t)(n0 + row)       * HALF_FFN + lc;
    }

    int warpId = tid >> 5;
    int wm = (warpId & 3) * 32;
    int wn = (warpId >> 2) * 64;

    FragC acc[2][4];
#pragma unroll
    for (int i = 0; i < 2; i++)
#pragma unroll
        for (int j = 0; j < 4; j++) wmma::fill_fragment(acc[i][j], 0.f);

    float4 rg[4], ru[4], rb[4];
#pragma unroll
    for (int p = 0; p < 4; p++) {
        rg[p] = *(const float4*)(hptr[p]);
        ru[p] = *(const float4*)(hptr[p] + HALF_FFN);
        rb[p] = *(const float4*)(bptr[p]);
    }

    const int KT = HALF_FFN / BK;   // 128
#pragma unroll 1
    for (int kt = 0; kt < KT; kt++) {
#pragma unroll
        for (int p = 0; p < 4; p++) {
            int row = lr + 32 * p;
            float4 g = rg[p], u = ru[p], v;
            v.x = g.x * (1.f / (1.f + __expf(-g.x))) * u.x;
            v.y = g.y * (1.f / (1.f + __expf(-g.y))) * u.y;
            v.z = g.z * (1.f / (1.f + __expf(-g.z))) * u.z;
            v.w = g.w * (1.f / (1.f + __expf(-g.w))) * u.w;
            *(float4*)(As + row * LDS + lc) = v;
            *(float4*)(Bs + row * LDS + lc) = rb[p];
        }
        __syncthreads();
        if (kt + 1 < KT) {
            int k0 = (kt + 1) * BK;
#pragma unroll
            for (int p = 0; p < 4; p++) {
                rg[p] = *(const float4*)(hptr[p] + k0);
                ru[p] = *(const float4*)(hptr[p] + HALF_FFN + k0);
                rb[p] = *(const float4*)(bptr[p] + k0);
            }
        }
#pragma unroll
        for (int ks = 0; ks < BK / 8; ks++) {
            FragA af[2]; FragB bf[4];
#pragma unroll
            for (int i = 0; i < 2; i++) {
                wmma::load_matrix_sync(af[i], As + (wm + i * 16) * LDS + ks * 8, LDS);
                to_tf32(af[i]);
            }
#pragma unroll
            for (int j = 0; j < 4; j++) {
                wmma::load_matrix_sync(bf[j], Bs + (wn + j * 16) * LDS + ks * 8, LDS);
                to_tf32(bf[j]);
            }
#pragma unroll
            for (int i = 0; i < 2; i++)
#pragma unroll
                for (int j = 0; j < 4; j++)
                    wmma::mma_sync(acc[i][j], af[i], bf[j], acc[i][j]);
        }
        __syncthreads();
    }

#pragma unroll
    for (int i = 0; i < 2; i++)
#pragma unroll
        for (int j = 0; j < 4; j++)
            wmma::store_matrix_sync(Cs + (wm + i * 16) * BN + (wn + j * 16),
                                    acc[i][j], BN, wmma::mem_row_major);
    __syncthreads();

#pragma unroll
    for (int p = 0; p < 16; p++) {
        int idx = tid + p * 256;
        int row = idx >> 5;
        int col = (idx & 31) * 4;
        if (row < rows_valid) {
            float c = s_coef[row];
            float4 v = *(const float4*)(Cs + row * BN + col);
            v.x *= c; v.y *= c; v.z *= c; v.w *= c;
            *(float4*)(g_Y + ((size_t)s_slot[row] * T_TOKENS + s_tok[row]) * D_MODEL
                           + n0 + col) = v;
        }
    }
}

__global__ void combine_kernel(float* __restrict__ out) {
    size_t i = (size_t)blockIdx.x * blockDim.x + threadIdx.x;
    const size_t n4 = (size_t)T_TOKENS * D_MODEL / 4;
    if (i < n4) {
        const float4* y = (const float4*)g_Y;
        float4 a = y[i], b = y[i + n4];
        float4 r;
        r.x = a.x + b.x; r.y = a.y + b.y; r.z = a.z + b.z; r.w = a.w + b.w;
        ((float4*)out)[i] = r;
    }
}

// ---------------- host entry -------------------------------------------------
extern "C" void kernel_launch(void* const* d_in, const int* in_sizes, int n_in,
                              void* d_out, int out_size) {
    const float* x      = (const float*)d_in[0];
    const float* gate_w = (const float*)d_in[1];
    const float* w_up   = (const float*)d_in[2];
    const float* w_down = (const float*)d_in[3];
    float* out = (float*)d_out;

    cudaFuncSetAttribute(up_gemm_kernel,
                         cudaFuncAttributeMaxDynamicSharedMemorySize, GEMM_SMEM);
    cudaFuncSetAttribute(down_gemm_kernel,
                         cudaFuncAttributeMaxDynamicSharedMemorySize, GEMM_SMEM);

    reset_kernel<<<1, 32>>>();
    routing_kernel<<<T_TOKENS / 8, 256>>>(x, gate_w);
    offs_kernel<<<1, 1>>>();
    compact_kernel<<<NE, 1024>>>();

    // up: N = FFN_DIM (64 n-tiles); m-tiles flattened across experts (max 136)
    up_gemm_kernel<<<dim3(FFN_DIM / BN, 136, 1), GEMM_THREADS, GEMM_SMEM>>>(x, w_up);
    // down: N = D_MODEL (16 n-tiles)
    down_gemm_kernel<<<dim3(D_MODEL / BN, 136, 1), GEMM_THREADS, GEMM_SMEM>>>(w_down);

    combine_kernel<<<(T_TOKENS * D_MODEL / 4 + 255) / 256, 256>>>(out);
}

// round 6
// speedup vs baseline: 1.3084x; 1.3084x over previous
#include <cuda_runtime.h>
#include <mma.h>
#include <cstdint>

using namespace nvcuda;

#define D_MODEL   2048
#define FFN_DIM   8192
#define HALF_FFN  4096
#define NE        8
#define T_TOKENS  8192
#define MAXROWS   (T_TOKENS * 2)

#define BM 128
#define BK 32
#define LDSF 36                        // 32 + 4 pad floats per smem row
#define DEPTH 3
#define STAGE_B (256 * LDSF * 4)       // A(128 rows) + B(128 rows) = 36864 B
#define DYN_SMEM (DEPTH * STAGE_B)     // 110592 B (epilogue C reuses this)

// ---------------- scratch (device globals; no runtime allocation) ----------
__device__ float g_A[(size_t)MAXROWS * HALF_FFN];       // 256 MB activated up outputs
__device__ float g_Y[(size_t)2 * T_TOKENS * D_MODEL];   // 128 MB per-slot down outputs
__device__ int   g_topk_idx[T_TOKENS][2];
__device__ float g_topk_w[T_TOKENS][2];
__device__ int   g_count[NE];
__device__ int   g_offs[NE + 1];
__device__ int   g_tile_offs[NE + 1];
__device__ int   g_list_token[MAXROWS];
__device__ int   g_list_slot[MAXROWS];
__device__ float g_list_coef[MAXROWS];

// ---------------- PTX helpers ------------------------------------------------
__device__ __forceinline__ uint32_t su32(const void* p) {
    uint32_t r;
    asm("{ .reg .u64 t; cvta.to.shared.u64 t, %1; cvt.u32.u64 %0, t; }"
        : "=r"(r) : "l"(p));
    return r;
}
__device__ __forceinline__ void cp16(uint32_t d, const void* s) {
    asm volatile("cp.async.cg.shared.global [%0], [%1], 16;\n"
                 :: "r"(d), "l"(s) : "memory");
}
__device__ __forceinline__ void cpcommit() {
    asm volatile("cp.async.commit_group;\n" ::: "memory");
}
__device__ __forceinline__ void cpwait2() {
    asm volatile("cp.async.wait_group 2;\n" ::: "memory");
}

// ---------------- TF32 wmma types -------------------------------------------
using FragA = wmma::fragment<wmma::matrix_a, 16, 16, 8, wmma::precision::tf32, wmma::row_major>;
using FragB = wmma::fragment<wmma::matrix_b, 16, 16, 8, wmma::precision::tf32, wmma::col_major>;
using FragC = wmma::fragment<wmma::accumulator, 16, 16, 8, float>;

template <typename Frag>
__device__ __forceinline__ void to_tf32(Frag& f) {
#pragma unroll
    for (int i = 0; i < f.num_elements; i++) f.x[i] = wmma::__float_to_tf32(f.x[i]);
}

__device__ __forceinline__ int find_expert(int ytile) {
    int e = 0;
#pragma unroll
    for (int i = 0; i < NE; i++) if (ytile >= g_tile_offs[i + 1]) e = i + 1;
    return e;
}

__device__ __forceinline__ float silu_mul(float g, float u) {
    return g * (1.f / (1.f + __expf(-g))) * u;
}

// ---------------- routing ----------------------------------------------------
__global__ void reset_kernel() {
    if (threadIdx.x < NE) g_count[threadIdx.x] = 0;
}

__global__ void routing_kernel(const float* __restrict__ x,
                               const float* __restrict__ gate_w) {
    int gwarp = (blockIdx.x * blockDim.x + threadIdx.x) >> 5;
    int lane  = threadIdx.x & 31;
    if (gwarp >= T_TOKENS) return;

    const float* xr = x + (size_t)gwarp * D_MODEL;
    float acc[NE];
#pragma unroll
    for (int e = 0; e < NE; e++) acc[e] = 0.f;
    for (int k = lane; k < D_MODEL; k += 32) {
        float xv = xr[k];
#pragma unroll
        for (int e = 0; e < NE; e++) acc[e] += xv * gate_w[e * D_MODEL + k];
    }
#pragma unroll
    for (int off = 16; off > 0; off >>= 1)
#pragma unroll
        for (int e = 0; e < NE; e++)
            acc[e] += __shfl_xor_sync(0xffffffffu, acc[e], off);

    if (lane == 0) {
        int i0 = 0; float b0 = acc[0];
#pragma unroll
        for (int i = 1; i < NE; i++) if (acc[i] > b0) { b0 = acc[i]; i0 = i; }
        int i1 = -1; float b1 = -3.0e38f;
#pragma unroll
        for (int i = 0; i < NE; i++)
            if (i != i0 && acc[i] > b1) { b1 = acc[i]; i1 = i; }
        float e1  = expf(b1 - b0);
        float inv = 1.f / (1.f + e1);
        g_topk_idx[gwarp][0] = i0;  g_topk_idx[gwarp][1] = i1;
        g_topk_w[gwarp][0]   = inv; g_topk_w[gwarp][1]   = e1 * inv;
        atomicAdd(&g_count[i0], 1);
        atomicAdd(&g_count[i1], 1);
    }
}

__global__ void offs_kernel() {
    if (threadIdx.x == 0 && blockIdx.x == 0) {
        int off = 0, toff = 0;
        for (int e = 0; e < NE; e++) {
            g_offs[e] = off; g_tile_offs[e] = toff;
            off  += g_count[e];
            toff += (g_count[e] + BM - 1) >> 7;
        }
        g_offs[NE] = off; g_tile_offs[NE] = toff;
    }
}

__global__ void compact_kernel() {
    int e   = blockIdx.x;
    int tid = threadIdx.x;
    __shared__ int s[1024];
    int base = g_offs[e];
    int run  = 0;
    for (int c0 = 0; c0 < T_TOKENS; c0 += 1024) {
        int t = c0 + tid;
        int sel = 0, slot = 0; float w = 0.f;
        if (t < T_TOKENS) {
            int i0 = g_topk_idx[t][0], i1 = g_topk_idx[t][1];
            if (i0 == e)      { sel = 1; slot = 0; w = g_topk_w[t][0]; }
            else if (i1 == e) { sel = 1; slot = 1; w = g_topk_w[t][1]; }
        }
        s[tid] = sel; __syncthreads();
        for (int d = 1; d < 1024; d <<= 1) {
            int v = (tid >= d) ? s[tid - d] : 0;
            __syncthreads();
            s[tid] += v;
            __syncthreads();
        }
        int incl  = s[tid];
        int total = s[1023];
        if (sel) {
            int r = base + run + incl - 1;
            g_list_token[r] = t;
            g_list_slot[r]  = slot;
            g_list_coef[r]  = w;
        }
        run += total;
        __syncthreads();
    }
}

// ---------------- UP GEMM (fused): g_A = silu(X Wg^T) * (X Wu^T) -------------
// grid (64 n-tiles of 64 over HALF_FFN, 136 m-tiles), block-swizzled in bands
// of 8 m-tiles. B stage: rows 0..63 = Wg rows, rows 64..127 = Wu rows.
__global__ void __launch_bounds__(256, 1)
up_gemm(const float* __restrict__ x, const float* __restrict__ w_up) {
    const int tiles_n = 64;
    int b    = blockIdx.y * tiles_n + blockIdx.x;
    int band = b / (8 * tiles_n);
    int rem  = b % (8 * tiles_n);
    int mt   = band * 8 + (rem & 7);
    int nt   = rem >> 3;
    if (mt >= g_tile_offs[NE]) return;

    int e  = find_expert(mt);
    int m0 = (mt - g_tile_offs[e]) * BM;
    int rows = g_count[e] - m0; if (rows > BM) rows = BM;
    int base = g_offs[e];
    int n0   = nt * 64;
    int tid  = threadIdx.x, wid = tid >> 5;

    __shared__ int s_tok[BM];
    extern __shared__ __align__(16) float dynf[];
    uint32_t dbase = su32(dynf);

    if (tid < BM) {
        int rr = (tid < rows) ? tid : (rows - 1);
        s_tok[tid] = g_list_token[base + m0 + rr];
    }
    __syncthreads();

    const float* we = w_up + (size_t)e * FFN_DIM * D_MODEL;
    int r0 = tid >> 3, q = tid & 7;
    const char* ap[4];
    const char* bp[4];
    uint32_t da[4], dbw[4];
#pragma unroll
    for (int p = 0; p < 4; p++) {
        int r = r0 + 32 * p;
        ap[p] = (const char*)(x + (size_t)s_tok[r] * D_MODEL) + q * 16;
        int brow = (p < 2) ? (n0 + r) : (HALF_FFN + n0 + (r - 64));
        bp[p] = (const char*)(we + (size_t)brow * D_MODEL) + q * 16;
        da[p]  = (uint32_t)(r * (LDSF * 4) + q * 16);
        dbw[p] = (uint32_t)(BM * (LDSF * 4) + r * (LDSF * 4) + q * 16);
    }

    int wm = (wid & 3) * 32;          // 4 m-strips of 32
    int wn = (wid >> 2) * 32;         // 2 n-strips of 32

    FragC accg[2][2], accu[2][2];
#pragma unroll
    for (int i = 0; i < 2; i++)
#pragma unroll
        for (int j = 0; j < 2; j++) {
            wmma::fill_fragment(accg[i][j], 0.f);
            wmma::fill_fragment(accu[i][j], 0.f);
        }

    const int KT = D_MODEL / BK;      // 64

#define UP_ISSUE(J) do {                                                     \
    uint32_t sb = dbase + ((J) % DEPTH) * STAGE_B;                           \
    size_t ko = (size_t)(J) * 128;                                           \
    _Pragma("unroll")                                                        \
    for (int p = 0; p < 4; p++) {                                            \
        cp16(sb + da[p],  ap[p] + ko);                                       \
        cp16(sb + dbw[p], bp[p] + ko);                                       \
    }                                                                        \
    cpcommit();                                                              \
} while (0)

    UP_ISSUE(0);
    UP_ISSUE(1);

#pragma unroll 1
    for (int kt = 0; kt < KT; kt++) {
        int jn = kt + DEPTH - 1;
        if (jn < KT) { UP_ISSUE(jn); } else { cpcommit(); }
        cpwait2();
        __syncthreads();

        float* As = dynf + (kt % DEPTH) * (STAGE_B / 4);
        float* Bs = As + BM * LDSF;
#pragma unroll
        for (int ks = 0; ks < BK / 8; ks++) {
            FragA af[2]; FragB bg[2], bu[2];
#pragma unroll
            for (int i = 0; i < 2; i++) {
                wmma::load_matrix_sync(af[i], As + (wm + i * 16) * LDSF + ks * 8, LDSF);
                to_tf32(af[i]);
            }
#pragma unroll
            for (int j = 0; j < 2; j++) {
                wmma::load_matrix_sync(bg[j], Bs + (wn + j * 16) * LDSF + ks * 8, LDSF);
                to_tf32(bg[j]);
                wmma::load_matrix_sync(bu[j], Bs + (64 + wn + j * 16) * LDSF + ks * 8, LDSF);
                to_tf32(bu[j]);
            }
#pragma unroll
            for (int i = 0; i < 2; i++)
#pragma unroll
                for (int j = 0; j < 2; j++) {
                    wmma::mma_sync(accg[i][j], af[i], bg[j], accg[i][j]);
                    wmma::mma_sync(accu[i][j], af[i], bu[j], accu[i][j]);
                }
        }
        __syncthreads();
    }
#undef UP_ISSUE

    // epilogue: silu(Cg)*Cu -> g_A   (Cg, Cu staged in smem, 32 KB each)
    float* Cg = dynf;
    float* Cu = dynf + 128 * 64;
#pragma unroll
    for (int i = 0; i < 2; i++)
#pragma unroll
        for (int j = 0; j < 2; j++) {
            wmma::store_matrix_sync(Cg + (wm + i * 16) * 64 + wn + j * 16,
                                    accg[i][j], 64, wmma::mem_row_major);
            wmma::store_matrix_sync(Cu + (wm + i * 16) * 64 + wn + j * 16,
                                    accu[i][j], 64, wmma::mem_row_major);
        }
    __syncthreads();

#pragma unroll
    for (int it = 0; it < 8; it++) {
        int idx = tid + it * 256;
        int row = idx >> 4;
        int col = (idx & 15) * 4;
        if (row < rows) {
            float4 g = *(const float4*)(Cg + row * 64 + col);
            float4 u = *(const float4*)(Cu + row * 64 + col);
            float4 v;
            v.x = silu_mul(g.x, u.x);
            v.y = silu_mul(g.y, u.y);
            v.z = silu_mul(g.z, u.z);
            v.w = silu_mul(g.w, u.w);
            *(float4*)(g_A + (size_t)(base + m0 + row) * HALF_FFN + n0 + col) = v;
        }
    }
}

// ---------------- DOWN GEMM: g_Y[slot] = coef * (g_A Wdown^T) ----------------
// grid (16 n-tiles of 128 over D_MODEL, 136 m-tiles), same band swizzle.
__global__ void __launch_bounds__(256, 1)
down_gemm(const float* __restrict__ w_down) {
    const int tiles_n = 16;
    int b    = blockIdx.y * tiles_n + blockIdx.x;
    int band = b / (8 * tiles_n);
    int rem  = b % (8 * tiles_n);
    int mt   = band * 8 + (rem & 7);
    int nt   = rem >> 3;
    if (mt >= g_tile_offs[NE]) return;

    int e  = find_expert(mt);
    int m0 = (mt - g_tile_offs[e]) * BM;
    int rows = g_count[e] - m0; if (rows > BM) rows = BM;
    int base = g_offs[e];
    int n0   = nt * 128;
    int tid  = threadIdx.x, wid = tid >> 5;

    __shared__ int   s_tk[BM];
    __shared__ int   s_sl[BM];
    __shared__ float s_cf[BM];
    extern __shared__ __align__(16) float dynf[];
    uint32_t dbase = su32(dynf);

    if (tid < BM) {
        if (tid < rows) {
            s_tk[tid] = g_list_token[base + m0 + tid];
            s_sl[tid] = g_list_slot[base + m0 + tid];
            s_cf[tid] = g_list_coef[base + m0 + tid];
        } else { s_tk[tid] = 0; s_sl[tid] = 0; s_cf[tid] = 0.f; }
    }
    __syncthreads();

    const float* we = w_down + (size_t)e * D_MODEL * HALF_FFN;
    int r0 = tid >> 3, q = tid & 7;
    const char* ap[4];
    const char* bp[4];
    uint32_t da[4], dbw[4];
#pragma unroll
    for (int p = 0; p < 4; p++) {
        int r = r0 + 32 * p;
        int ar = (r < rows) ? r : (rows - 1);
        ap[p] = (const char*)(g_A + (size_t)(base + m0 + ar) * HALF_FFN) + q * 16;
        bp[p] = (const char*)(we + (size_t)(n0 + r) * HALF_FFN) + q * 16;
        da[p]  = (uint32_t)(r * (LDSF * 4) + q * 16);
        dbw[p] = (uint32_t)(BM * (LDSF * 4) + r * (LDSF * 4) + q * 16);
    }

    int wm = (wid & 3) * 32;          // 4 m-strips of 32
    int wn = (wid >> 2) * 64;         // 2 n-strips of 64

    FragC acc[2][4];
#pragma unroll
    for (int i = 0; i < 2; i++)
#pragma unroll
        for (int j = 0; j < 4; j++) wmma::fill_fragment(acc[i][j], 0.f);

    const int KT = HALF_FFN / BK;     // 128

#define DN_ISSUE(J) do {                                                     \
    uint32_t sb = dbase + ((J) % DEPTH) * STAGE_B;                           \
    size_t ko = (size_t)(J) * 128;                                           \
    _Pragma("unroll")                                                        \
    for (int p = 0; p < 4; p++) {                                            \
        cp16(sb + da[p],  ap[p] + ko);                                       \
        cp16(sb + dbw[p], bp[p] + ko);                                       \
    }                                                                        \
    cpcommit();                                                              \
} while (0)

    DN_ISSUE(0);
    DN_ISSUE(1);

#pragma unroll 1
    for (int kt = 0; kt < KT; kt++) {
        int jn = kt + DEPTH - 1;
        if (jn < KT) { DN_ISSUE(jn); } else { cpcommit(); }
        cpwait2();
        __syncthreads();

        float* As = dynf + (kt % DEPTH) * (STAGE_B / 4);
        float* Bs = As + BM * LDSF;
#pragma unroll
        for (int ks = 0; ks < BK / 8; ks++) {
            FragA af[2]; FragB bf[4];
#pragma unroll
            for (int i = 0; i < 2; i++) {
                wmma::load_matrix_sync(af[i], As + (wm + i * 16) * LDSF + ks * 8, LDSF);
                to_tf32(af[i]);
            }
#pragma unroll
            for (int j = 0; j < 4; j++) {
                wmma::load_matrix_sync(bf[j], Bs + (wn + j * 16) * LDSF + ks * 8, LDSF);
                to_tf32(bf[j]);
            }
#pragma unroll
            for (int i = 0; i < 2; i++)
#pragma unroll
                for (int j = 0; j < 4; j++)
                    wmma::mma_sync(acc[i][j], af[i], bf[j], acc[i][j]);
        }
        __syncthreads();
    }
#undef DN_ISSUE

    // epilogue: scale by coef, scatter to g_Y (C staged in smem, 64 KB)
    float* Cs = dynf;
#pragma unroll
    for (int i = 0; i < 2; i++)
#pragma unroll
        for (int j = 0; j < 4; j++)
            wmma::store_matrix_sync(Cs + (wm + i * 16) * 128 + wn + j * 16,
                                    acc[i][j], 128, wmma::mem_row_major);
    __syncthreads();

#pragma unroll
    for (int it = 0; it < 16; it++) {
        int idx = tid + it * 256;
        int row = idx >> 5;
        int col = (idx & 31) * 4;
        if (row < rows) {
            float c = s_cf[row];
            float4 v = *(const float4*)(Cs + row * 128 + col);
            v.x *= c; v.y *= c; v.z *= c; v.w *= c;
            *(float4*)(g_Y + ((size_t)s_sl[row] * T_TOKENS + s_tk[row]) * D_MODEL
                           + n0 + col) = v;
        }
    }
}

__global__ void combine_kernel(float* __restrict__ out) {
    size_t i = (size_t)blockIdx.x * blockDim.x + threadIdx.x;
    const size_t n4 = (size_t)T_TOKENS * D_MODEL / 4;
    if (i < n4) {
        const float4* y = (const float4*)g_Y;
        float4 a = y[i], b = y[i + n4];
        float4 r;
        r.x = a.x + b.x; r.y = a.y + b.y; r.z = a.z + b.z; r.w = a.w + b.w;
        ((float4*)out)[i] = r;
    }
}

// ---------------- host entry -------------------------------------------------
extern "C" void kernel_launch(void* const* d_in, const int* in_sizes, int n_in,
                              void* d_out, int out_size) {
    const float* x      = (const float*)d_in[0];
    const float* gate_w = (const float*)d_in[1];
    const float* w_up   = (const float*)d_in[2];
    const float* w_down = (const float*)d_in[3];
    float* out = (float*)d_out;

    cudaFuncSetAttribute(up_gemm,   cudaFuncAttributeMaxDynamicSharedMemorySize, DYN_SMEM);
    cudaFuncSetAttribute(down_gemm, cudaFuncAttributeMaxDynamicSharedMemorySize, DYN_SMEM);

    reset_kernel<<<1, 32>>>();
    routing_kernel<<<T_TOKENS / 8, 256>>>(x, gate_w);
    offs_kernel<<<1, 1>>>();
    compact_kernel<<<NE, 1024>>>();

    // up: 64 n-tiles (64 cols of HALF_FFN each, g+u) x 136 m-tiles
    up_gemm<<<dim3(64, 136, 1), 256, DYN_SMEM>>>(x, w_up);
    // down: 16 n-tiles (128 cols of D_MODEL) x 136 m-tiles
    down_gemm<<<dim3(16, 136, 1), 256, DYN_SMEM>>>(w_down);

    combine_kernel<<<(T_TOKENS * D_MODEL / 4 + 255) / 256, 256>>>(out);
}